// round 13
// baseline (speedup 1.0000x reference)
#include <cuda_runtime.h>
#include <cuda_fp16.h>
#include <cstdint>
#include <math.h>

#define Bb 8
#define Cc 512
#define Tt 1024
#define BCT (Bb*Cc*Tt)
#define BTT (Bb*Tt*Tt)

// chunked fp16 layout: [ch][R rows][128B], per-row swizzle on byte offsets:
// byte(col,row) = bytecol ^ ((row&7)<<4)
#define ZB16 ((size_t)16*1024*128)
#define VB   ((size_t)16*512*128)
#define AB   ((size_t)16*1024*128)
#define OB   ((size_t)8*1024*128)
#define WBY  ((size_t)8*512*128)
// int8 q/k digit planes: 8 chunks (re 0-3, im 4-7) x 1024 rows x 128 int8
#define QK8  ((size_t)8*1024*128)

__device__ __align__(16) unsigned char g_zh[Bb*ZB16], g_zl[Bb*ZB16];
__device__ __align__(16) signed char g_q8h[Bb*QK8], g_q8m[Bb*QK8];
__device__ __align__(16) signed char g_k8h[Bb*QK8], g_k8m[Bb*QK8];
__device__ __align__(16) unsigned char g_vreh[Bb*VB], g_vimh[Bb*VB];
__device__ __align__(16) unsigned char g_ath[Bb*AB];
__device__ __align__(16) unsigned char g_oreh[Bb*OB], g_oimh[Bb*OB];
__device__ __align__(16) unsigned char g_wh[4*WBY],   g_wl[4*WBY];
__device__ float g_attn[BTT];

#define SW128(o) ((o) ^ (((o) >> 3) & 0x70))
#define CPT 256

__device__ __forceinline__ uint32_t s2u(const void* p) {
    uint32_t a;
    asm("{ .reg .u64 t; cvta.to.shared.u64 t, %1; cvt.u32.u64 %0, t; }" : "=r"(a) : "l"(p));
    return a;
}
__device__ __forceinline__ uint32_t pk2(__half a, __half b) {
    return ((uint32_t)__half_as_ushort(b) << 16) | (uint32_t)__half_as_ushort(a);
}
__device__ __forceinline__ void st_pair(unsigned char* bh, unsigned char* bl,
                                        int R, int ch, int row, int col, float v0, float v1) {
    size_t off = (((size_t)ch * R + row) << 7) + (uint32_t)((col * 2) ^ ((row & 7) << 4));
    __half h0 = __float2half_rn(v0), h1 = __float2half_rn(v1);
    *(uint32_t*)(bh + off) = pk2(h0, h1);
    __half l0 = __float2half_rn(v0 - __half2float(h0));
    __half l1 = __float2half_rn(v1 - __half2float(h1));
    *(uint32_t*)(bl + off) = pk2(l0, l1);
}
__device__ __forceinline__ void st_one(unsigned char* bh,
                                       int R, int ch, int row, int col, float v0, float v1) {
    size_t off = (((size_t)ch * R + row) << 7) + (uint32_t)((col * 2) ^ ((row & 7) << 4));
    *(uint32_t*)(bh + off) = pk2(__float2half_rn(v0), __float2half_rn(v1));
}
// quantize pair of values to 16-bit ints, store h/m int8 digit planes.
// cglob = global channel (0..511); chbase = 0 (re) or 4 (im).
__device__ __forceinline__ void st_q8(signed char* ph, signed char* pm,
                                      int chbase, int cglob, int row, float v0, float v1) {
    const int ch = chbase + (cglob >> 7);
    const int colb = cglob & 127;
    size_t off = (((size_t)ch * 1024 + row) << 7) + (uint32_t)(colb ^ ((row & 7) << 4));
    int w0 = __float2int_rn(v0 * 4096.f);
    int w1 = __float2int_rn(v1 * 4096.f);
    w0 = max(-32639, min(32639, w0));
    w1 = max(-32639, min(32639, w1));
    int h0 = (w0 + 128) >> 8, h1 = (w1 + 128) >> 8;
    int m0 = w0 - (h0 << 8), m1 = w1 - (h1 << 8);
    *(char2*)(ph + off) = make_char2((signed char)h0, (signed char)h1);
    *(char2*)(pm + off) = make_char2((signed char)m0, (signed char)m1);
}
__device__ __forceinline__ void cpa16(uint32_t s, const void* g) {
    asm volatile("cp.async.cg.shared.global [%0], [%1], 16;" :: "r"(s), "l"(g) : "memory");
}
__device__ __forceinline__ void cpa_commit() { asm volatile("cp.async.commit_group;" ::: "memory"); }
__device__ __forceinline__ void cpa_wait1()  { asm volatile("cp.async.wait_group 1;" ::: "memory"); }
__device__ __forceinline__ void cpa_wait0()  { asm volatile("cp.async.wait_group 0;" ::: "memory"); }
__device__ __forceinline__ void cpreg(uint32_t s, const void* g, int nbytes, int tid) {
    for (int o = tid * 16; o < nbytes; o += CPT * 16) cpa16(s + o, (const unsigned char*)g + o);
}
__device__ __forceinline__ void ldsm4(uint32_t* r, uint32_t addr) {
    asm volatile("ldmatrix.sync.aligned.m8n8.x4.shared.b16 {%0,%1,%2,%3}, [%4];"
                 : "=r"(r[0]), "=r"(r[1]), "=r"(r[2]), "=r"(r[3]) : "r"(addr));
}
__device__ __forceinline__ void mma16816(float* d, const uint32_t* a, const uint32_t* b) {
    asm volatile(
        "mma.sync.aligned.m16n8k16.row.col.f32.f16.f16.f32 "
        "{%0,%1,%2,%3}, {%4,%5,%6,%7}, {%8,%9}, {%0,%1,%2,%3};"
        : "+f"(d[0]), "+f"(d[1]), "+f"(d[2]), "+f"(d[3])
        : "r"(a[0]), "r"(a[1]), "r"(a[2]), "r"(a[3]), "r"(b[0]), "r"(b[1]));
}
// int8 k32 MMA, s32 accumulate
__device__ __forceinline__ void mma_s8(int* d, const uint32_t* a, const uint32_t* b) {
    asm volatile(
        "mma.sync.aligned.m16n8k32.row.col.s32.s8.s8.s32 "
        "{%0,%1,%2,%3}, {%4,%5,%6,%7}, {%8,%9}, {%0,%1,%2,%3};"
        : "+r"(d[0]), "+r"(d[1]), "+r"(d[2]), "+r"(d[3])
        : "r"(a[0]), "r"(a[1]), "r"(a[2]), "r"(a[3]), "r"(b[0]), "r"(b[1]));
}
__device__ __forceinline__ void mma_split(float* d, const uint32_t* aH, const uint32_t* aL,
                                          const uint32_t* bH, const uint32_t* bL) {
    mma16816(d, aH, bH);
    mma16816(d, aH, bL);
    mma16816(d, aL, bH);
}
__device__ __forceinline__ uint32_t a_addr(uint32_t base, int mbase, int ks, int lane) {
    int row = mbase + (lane & 15);
    int byt = ks * 32 + ((lane >> 4) << 4);
    return base + SW128((uint32_t)(row * 128 + byt));
}
__device__ __forceinline__ uint32_t b_addr(uint32_t base, int nbase, int ks, int lane) {
    int row = nbase + ((lane >> 4) << 3) + (lane & 7);
    int byt = ks * 32 + (((lane >> 3) & 1) << 4);
    return base + SW128((uint32_t)(row * 128 + byt));
}

// ---------------------------------------------------------------------------
__global__ __launch_bounds__(256) void prep_z(
    const float* __restrict__ zre, const float* __restrict__ zim)
{
    __shared__ float sre[64][33], sim[64][33];
    const int b = blockIdx.z, t0 = blockIdx.x * 32, c0 = blockIdx.y * 64;
    const int tid = threadIdx.x;
    const float* pre = zre + (size_t)b * Cc * Tt;
    const float* pim = zim + (size_t)b * Cc * Tt;
    for (int i = tid; i < 2048; i += 256) {
        int cl = i >> 5, tl = i & 31;
        sre[cl][tl] = pre[(size_t)(c0 + cl) * Tt + t0 + tl];
        sim[cl][tl] = pim[(size_t)(c0 + cl) * Tt + t0 + tl];
    }
    __syncthreads();
    unsigned char* zh = g_zh + (size_t)b * ZB16;
    unsigned char* zl = g_zl + (size_t)b * ZB16;
    const int ch = c0 >> 6;
    for (int i = tid; i < 1024; i += 256) {
        int tl = i >> 5, p = i & 31;
        int t = t0 + tl, col = p * 2;
        st_pair(zh, zl, 1024, ch,     t, col, sre[col][tl], sre[col + 1][tl]);
        st_pair(zh, zl, 1024, ch + 8, t, col, sim[col][tl], sim[col + 1][tl]);
    }
}

// ---------------------------------------------------------------------------
__global__ __launch_bounds__(256) void prep_w(
    const float* __restrict__ W0, const float* __restrict__ W1,
    const float* __restrict__ W2, const float* __restrict__ W3)
{
    const int d0 = blockIdx.x * 64, wi = blockIdx.y, tid = threadIdx.x;
    const float* W = (wi == 0) ? W0 : (wi == 1) ? W1 : (wi == 2) ? W2 : W3;
    unsigned char* oh = g_wh + (size_t)wi * WBY;
    unsigned char* ol = g_wl + (size_t)wi * WBY;
    for (int i = tid; i < 8192; i += 256) {
        int dl = i >> 7, q = i & 127;
        int c = q * 4, d = d0 + dl;
        float4 v = *(const float4*)&W[(size_t)d * Cc + c];
        st_pair(oh, ol, 512, c >> 6, d, c & 63, v.x, v.y);
        st_pair(oh, ol, 512, c >> 6, d, (c & 63) + 2, v.z, v.w);
    }
}

// ---------------------------------------------------------------------------
// gemm_qk2: fused Q+K projection, 3-term fp16 f32 acc. Epilogue quantizes
// to int8 digit planes (h,m; v = q*4096 = 256h+m) for the int8 scores GEMM.
// CTA 128(t)x64(d), 8 warps = 4m x 2n, warp 32x32 for BOTH Q and K.
// grid (8, 8, Bb). smem 2 x 96KB.
// ---------------------------------------------------------------------------
#define QK2_STRIDE 98304
#define QK2_SM (2*QK2_STRIDE)
__global__ __launch_bounds__(256) void gemm_qk2(
    const float* __restrict__ phi_q, const float* __restrict__ phi_k)
{
    extern __shared__ char sm[];
    __shared__ float csq[64], snq[64], csk[64], snk[64];
    const uint32_t smb = s2u(sm);
    const int tid = threadIdx.x, wid = tid >> 5, lane = tid & 31;
    const int wm = wid & 3, wn = wid >> 2;
    const int b = blockIdx.z, m0 = blockIdx.y * 128, n0 = blockIdx.x * 64;

    if (tid < 64) {
        float s, c;
        sincosf(phi_q[n0 + tid], &s, &c); csq[tid] = c; snq[tid] = s;
        sincosf(phi_k[n0 + tid], &s, &c); csk[tid] = c; snk[tid] = s;
    }

    const unsigned char* zh = g_zh + (size_t)b * ZB16;
    const unsigned char* zl = g_zl + (size_t)b * ZB16;
    const unsigned char* wqh = g_wh;
    const unsigned char* wql = g_wl;
    const unsigned char* wkh = g_wh + WBY;
    const unsigned char* wkl = g_wl + WBY;

    auto issue = [&](int ch, uint32_t bs) {
        size_t aoR = ((size_t)(ch * 1024 + m0)) << 7;
        size_t aoI = ((size_t)((ch + 8) * 1024 + m0)) << 7;
        size_t bo  = ((size_t)(ch * 512 + n0)) << 7;
        cpreg(bs + 0,     zh + aoR, 16384, tid);
        cpreg(bs + 16384, zl + aoR, 16384, tid);
        cpreg(bs + 32768, zh + aoI, 16384, tid);
        cpreg(bs + 49152, zl + aoI, 16384, tid);
        cpreg(bs + 65536, wqh + bo, 8192, tid);
        cpreg(bs + 73728, wql + bo, 8192, tid);
        cpreg(bs + 81920, wkh + bo, 8192, tid);
        cpreg(bs + 90112, wkl + bo, 8192, tid);
    };

    float accQR[2][4][4] = {}, accQI[2][4][4] = {};
    float accKR[2][4][4] = {}, accKI[2][4][4] = {};
    issue(0, smb); cpa_commit();
    for (int ch = 0; ch < 8; ch++) {
        uint32_t base = smb + (ch & 1) * QK2_STRIDE;
        if (ch + 1 < 8) { issue(ch + 1, smb + ((ch + 1) & 1) * QK2_STRIDE); cpa_commit(); cpa_wait1(); }
        else cpa_wait0();
        __syncthreads();
        #pragma unroll
        for (int ks = 0; ks < 4; ks++) {
            uint32_t arH[8], arL[8], aiH[8], aiL[8];
            ldsm4(arH + 0, a_addr(base + 0,     wm * 32,      ks, lane));
            ldsm4(arH + 4, a_addr(base + 0,     wm * 32 + 16, ks, lane));
            ldsm4(arL + 0, a_addr(base + 16384, wm * 32,      ks, lane));
            ldsm4(arL + 4, a_addr(base + 16384, wm * 32 + 16, ks, lane));
            ldsm4(aiH + 0, a_addr(base + 32768, wm * 32,      ks, lane));
            ldsm4(aiH + 4, a_addr(base + 32768, wm * 32 + 16, ks, lane));
            ldsm4(aiL + 0, a_addr(base + 49152, wm * 32,      ks, lane));
            ldsm4(aiL + 4, a_addr(base + 49152, wm * 32 + 16, ks, lane));
            uint32_t bH[8], bL[8];
            ldsm4(bH + 0, b_addr(base + 65536, wn * 32,      ks, lane));
            ldsm4(bH + 4, b_addr(base + 65536, wn * 32 + 16, ks, lane));
            ldsm4(bL + 0, b_addr(base + 73728, wn * 32,      ks, lane));
            ldsm4(bL + 4, b_addr(base + 73728, wn * 32 + 16, ks, lane));
            #pragma unroll
            for (int mi = 0; mi < 2; mi++)
                #pragma unroll
                for (int nf = 0; nf < 4; nf++) {
                    mma_split(accQR[mi][nf], arH + mi * 4, arL + mi * 4, bH + nf * 2, bL + nf * 2);
                    mma_split(accQI[mi][nf], aiH + mi * 4, aiL + mi * 4, bH + nf * 2, bL + nf * 2);
                }
            ldsm4(bH + 0, b_addr(base + 81920, wn * 32,      ks, lane));
            ldsm4(bH + 4, b_addr(base + 81920, wn * 32 + 16, ks, lane));
            ldsm4(bL + 0, b_addr(base + 90112, wn * 32,      ks, lane));
            ldsm4(bL + 4, b_addr(base + 90112, wn * 32 + 16, ks, lane));
            #pragma unroll
            for (int mi = 0; mi < 2; mi++)
                #pragma unroll
                for (int nf = 0; nf < 4; nf++) {
                    mma_split(accKR[mi][nf], arH + mi * 4, arL + mi * 4, bH + nf * 2, bL + nf * 2);
                    mma_split(accKI[mi][nf], aiH + mi * 4, aiL + mi * 4, bH + nf * 2, bL + nf * 2);
                }
        }
        __syncthreads();
    }

    signed char* qph = g_q8h + (size_t)b * QK8;
    signed char* qpm = g_q8m + (size_t)b * QK8;
    signed char* kph = g_k8h + (size_t)b * QK8;
    signed char* kpm = g_k8m + (size_t)b * QK8;
    const int g = lane >> 2, cp = (lane & 3) * 2;
    #pragma unroll
    for (int mi = 0; mi < 2; mi++) {
        const int r0 = m0 + wm * 32 + mi * 16 + g;
        #pragma unroll
        for (int nf = 0; nf < 4; nf++) {
            const int c = wn * 32 + nf * 8 + cp;
            const int cg = n0 + c;
            float cq0 = csq[c], sq0 = snq[c], cq1 = csq[c + 1], sq1 = snq[c + 1];
            float ck0 = csk[c], sk0 = snk[c], ck1 = csk[c + 1], sk1 = snk[c + 1];
            float* qR = accQR[mi][nf]; float* qI = accQI[mi][nf];
            float* kR = accKR[mi][nf]; float* kI = accKI[mi][nf];
            st_q8(qph, qpm, 0, cg, r0, qR[0]*cq0 - qI[0]*sq0, qR[1]*cq1 - qI[1]*sq1);
            st_q8(qph, qpm, 4, cg, r0, qR[0]*sq0 + qI[0]*cq0, qR[1]*sq1 + qI[1]*cq1);
            st_q8(qph, qpm, 0, cg, r0 + 8, qR[2]*cq0 - qI[2]*sq0, qR[3]*cq1 - qI[3]*sq1);
            st_q8(qph, qpm, 4, cg, r0 + 8, qR[2]*sq0 + qI[2]*cq0, qR[3]*sq1 + qI[3]*cq1);
            st_q8(kph, kpm, 0, cg, r0, kR[0]*ck0 - kI[0]*sk0, kR[1]*ck1 - kI[1]*sk1);
            st_q8(kph, kpm, 4, cg, r0, kR[0]*sk0 + kI[0]*ck0, kR[1]*sk1 + kI[1]*ck1);
            st_q8(kph, kpm, 0, cg, r0 + 8, kR[2]*ck0 - kI[2]*sk0, kR[3]*ck1 - kI[3]*sk1);
            st_q8(kph, kpm, 4, cg, r0 + 8, kR[2]*sk0 + kI[2]*ck0, kR[3]*sk1 + kI[3]*ck1);
        }
    }
}

// ---------------------------------------------------------------------------
// gemm_scores (int8): S = sum v_q*v_k * 2^-24 / 8, v = 256h+m exact, via
// 4 s8 k32 MMAs (hh; hm+mh shared; mm). Concat K=1024 int8 = 8 chunks of 128.
// CTA 128(t) x 64(u), 8 warps = 4m x 2n, warp 32x32. grid (16, 8, Bb).
// smem stage = qh/qm 16KB each + kh/km 8KB each = 48KB, double = 96KB.
// ---------------------------------------------------------------------------
#define SC_STRIDE 49152
#define SC_SM (2*SC_STRIDE)
__global__ __launch_bounds__(256) void gemm_scores()
{
    extern __shared__ char sm[];
    const uint32_t smb = s2u(sm);
    const int tid = threadIdx.x, wid = tid >> 5, lane = tid & 31;
    const int wm = wid & 3, wn = wid >> 2;
    const int b = blockIdx.z, m0 = blockIdx.y * 128, n0 = blockIdx.x * 64;
    if (n0 >= m0 + 128) return;
    float* arow = g_attn + (size_t)b * Tt * Tt;

    const signed char* qph = g_q8h + (size_t)b * QK8;
    const signed char* qpm = g_q8m + (size_t)b * QK8;
    const signed char* kph = g_k8h + (size_t)b * QK8;
    const signed char* kpm = g_k8m + (size_t)b * QK8;

    auto issue = [&](int ch, uint32_t bs) {
        size_t ao = ((size_t)(ch * 1024 + m0)) << 7;
        size_t bo = ((size_t)(ch * 1024 + n0)) << 7;
        cpreg(bs + 0,     qph + ao, 16384, tid);
        cpreg(bs + 16384, qpm + ao, 16384, tid);
        cpreg(bs + 32768, kph + bo, 8192, tid);
        cpreg(bs + 40960, kpm + bo, 8192, tid);
    };

    int hh[2][4][4] = {}, hm[2][4][4] = {}, mm[2][4][4] = {};
    issue(0, smb); cpa_commit();
    for (int ch = 0; ch < 8; ch++) {
        uint32_t base = smb + (ch & 1) * SC_STRIDE;
        if (ch + 1 < 8) { issue(ch + 1, smb + ((ch + 1) & 1) * SC_STRIDE); cpa_commit(); cpa_wait1(); }
        else cpa_wait0();
        __syncthreads();
        #pragma unroll
        for (int ks = 0; ks < 4; ks++) {
            uint32_t kh[8], km[8];
            ldsm4(kh + 0, b_addr(base + 32768, wn * 32,      ks, lane));
            ldsm4(kh + 4, b_addr(base + 32768, wn * 32 + 16, ks, lane));
            ldsm4(km + 0, b_addr(base + 40960, wn * 32,      ks, lane));
            ldsm4(km + 4, b_addr(base + 40960, wn * 32 + 16, ks, lane));
            #pragma unroll
            for (int mi = 0; mi < 2; mi++) {
                uint32_t qh[4], qm[4];
                ldsm4(qh, a_addr(base + 0,     wm * 32 + mi * 16, ks, lane));
                ldsm4(qm, a_addr(base + 16384, wm * 32 + mi * 16, ks, lane));
                #pragma unroll
                for (int nf = 0; nf < 4; nf++) {
                    mma_s8(hh[mi][nf], qh, kh + nf * 2);
                    mma_s8(hm[mi][nf], qh, km + nf * 2);
                    mma_s8(hm[mi][nf], qm, kh + nf * 2);
                    mma_s8(mm[mi][nf], qm, km + nf * 2);
                }
            }
        }
        __syncthreads();
    }

    const int g = lane >> 2, cp = (lane & 3) * 2;
    const float sc = 0.125f / 16777216.f;  // 2^-24 * (1/8)
    #pragma unroll
    for (int mi = 0; mi < 2; mi++) {
        const int r0 = m0 + wm * 32 + mi * 16 + g;
        #pragma unroll
        for (int nf = 0; nf < 4; nf++) {
            const int u = n0 + wn * 32 + nf * 8 + cp;
            int* a1 = hh[mi][nf];
            int* a2 = hm[mi][nf];
            int* a3 = mm[mi][nf];
            float s0 = ((float)a1[0] * 65536.f + (float)a2[0] * 256.f + (float)a3[0]) * sc;
            float s1 = ((float)a1[1] * 65536.f + (float)a2[1] * 256.f + (float)a3[1]) * sc;
            float s2 = ((float)a1[2] * 65536.f + (float)a2[2] * 256.f + (float)a3[2]) * sc;
            float s3 = ((float)a1[3] * 65536.f + (float)a2[3] * 256.f + (float)a3[3]) * sc;
            *(float2*)&arow[(size_t)r0 * Tt + u]       = make_float2(s0, s1);
            *(float2*)&arow[(size_t)(r0 + 8) * Tt + u] = make_float2(s2, s3);
        }
    }
}

// ---------------------------------------------------------------------------
// gemm_wB: 1-term (W single fp16). D[d,n]=rot_row(W·Bᵀ).
// CTA 128(d) x 64(n), warps 4m x 2n (warp 32x32). grid (16, 4, Bb). smem 2x32KB.
// ---------------------------------------------------------------------------
#define WB_STRIDE 32768
#define WB_SM (2*WB_STRIDE)
template<bool F16OUT>
__global__ __launch_bounds__(256) void gemm_wB(
    const unsigned char* __restrict__ wh,
    const float* __restrict__ phi,
    const unsigned char* __restrict__ breh, const unsigned char* __restrict__ bimh,
    size_t bstride,
    float* __restrict__ fre, float* __restrict__ fim)
{
    extern __shared__ char sm[];
    __shared__ float s_cs[128], s_sn[128];
    const uint32_t smb = s2u(sm);
    const int tid = threadIdx.x, wid = tid >> 5, lane = tid & 31;
    const int wm = wid & 3, wn = wid >> 2;
    const int b = blockIdx.z, m0 = blockIdx.y * 128, n0 = blockIdx.x * 64;

    if (tid < 128) {
        float s, c; sincosf(phi[m0 + tid], &s, &c);
        s_cs[tid] = c; s_sn[tid] = s;
    }

    const unsigned char* brh = breh + (size_t)b * bstride;
    const unsigned char* bih = bimh + (size_t)b * bstride;

    auto issue = [&](int ch, uint32_t bs) {
        size_t ao = ((size_t)(ch * 512 + m0)) << 7;
        size_t bo = ((size_t)(ch * 1024 + n0)) << 7;
        cpreg(bs + 0,     wh + ao, 16384, tid);
        cpreg(bs + 16384, brh + bo, 8192, tid);
        cpreg(bs + 24576, bih + bo, 8192, tid);
    };

    float mR[2][4][4] = {}, mI[2][4][4] = {};
    issue(0, smb); cpa_commit();
    for (int ch = 0; ch < 8; ch++) {
        uint32_t base = smb + (ch & 1) * WB_STRIDE;
        if (ch + 1 < 8) { issue(ch + 1, smb + ((ch + 1) & 1) * WB_STRIDE); cpa_commit(); cpa_wait1(); }
        else cpa_wait0();
        __syncthreads();
        #pragma unroll
        for (int ks = 0; ks < 4; ks++) {
            uint32_t rH[8], iH[8];
            ldsm4(rH + 0, b_addr(base + 16384, wn * 32,      ks, lane));
            ldsm4(rH + 4, b_addr(base + 16384, wn * 32 + 16, ks, lane));
            ldsm4(iH + 0, b_addr(base + 24576, wn * 32,      ks, lane));
            ldsm4(iH + 4, b_addr(base + 24576, wn * 32 + 16, ks, lane));
            #pragma unroll
            for (int mi = 0; mi < 2; mi++) {
                uint32_t aH[4];
                ldsm4(aH, a_addr(base + 0, wm * 32 + mi * 16, ks, lane));
                #pragma unroll
                for (int nf = 0; nf < 4; nf++) {
                    mma16816(mR[mi][nf], aH, rH + nf * 2);
                    mma16816(mI[mi][nf], aH, iH + nf * 2);
                }
            }
        }
        __syncthreads();
    }

    const int g = lane >> 2, cp = (lane & 3) * 2;
    #pragma unroll
    for (int mi = 0; mi < 2; mi++) {
        const int lr = wm * 32 + mi * 16 + g;
        const float c0 = s_cs[lr], s0 = s_sn[lr], c8 = s_cs[lr + 8], s8 = s_sn[lr + 8];
        const int r0 = m0 + lr;
        #pragma unroll
        for (int nf = 0; nf < 4; nf++) {
            const int c = wn * 32 + nf * 8 + cp;
            float* aR = mR[mi][nf];
            float* aI = mI[mi][nf];
            float xr0 = aR[0]*c0 - aI[0]*s0, xr1 = aR[1]*c0 - aI[1]*s0;
            float xi0 = aR[0]*s0 + aI[0]*c0, xi1 = aR[1]*s0 + aI[1]*c0;
            float yr0 = aR[2]*c8 - aI[2]*s8, yr1 = aR[3]*c8 - aI[3]*s8;
            float yi0 = aR[2]*s8 + aI[2]*c8, yi1 = aR[3]*s8 + aI[3]*c8;
            if (F16OUT) {
                unsigned char* vrh = g_vreh + (size_t)b * VB;
                unsigned char* vih = g_vimh + (size_t)b * VB;
                const int och = (n0 + c) >> 6, oc = (n0 + c) & 63;
                st_one(vrh, 512, och, r0, oc, xr0, xr1);
                st_one(vih, 512, och, r0, oc, xi0, xi1);
                st_one(vrh, 512, och, r0 + 8, oc, yr0, yr1);
                st_one(vih, 512, och, r0 + 8, oc, yi0, yi1);
            } else {
                float* dre = fre + (size_t)b * Cc * Tt;
                float* dim = fim + (size_t)b * Cc * Tt;
                *(float2*)&dre[(size_t)r0 * Tt + n0 + c]       = make_float2(xr0, xr1);
                *(float2*)&dim[(size_t)r0 * Tt + n0 + c]       = make_float2(xi0, xi1);
                *(float2*)&dre[(size_t)(r0 + 8) * Tt + n0 + c] = make_float2(yr0, yr1);
                *(float2*)&dim[(size_t)(r0 + 8) * Tt + n0 + c] = make_float2(yi0, yi1);
            }
        }
    }
}

// ---------------------------------------------------------------------------
__global__ __launch_bounds__(256) void softmax_kernel()
{
    const int t = blockIdx.x, b = blockIdx.y;
    const float* row = g_attn + ((size_t)b * Tt + t) * Tt;
    const int tid = threadIdx.x;
    const float ni = __int_as_float(0xff800000);
    const int u0 = tid * 4;
    float4 v = ((const float4*)row)[tid];
    if (u0     > t) v.x = ni;
    if (u0 + 1 > t) v.y = ni;
    if (u0 + 2 > t) v.z = ni;
    if (u0 + 3 > t) v.w = ni;
    float m = fmaxf(fmaxf(v.x, v.y), fmaxf(v.z, v.w));
    __shared__ float red[8];
    #pragma unroll
    for (int o = 16; o > 0; o >>= 1) m = fmaxf(m, __shfl_xor_sync(0xffffffffu, m, o));
    if ((tid & 31) == 0) red[tid >> 5] = m;
    __syncthreads();
    if (tid == 0) {
        float mm = red[0];
        #pragma unroll
        for (int i = 1; i < 8; i++) mm = fmaxf(mm, red[i]);
        red[0] = mm;
    }
    __syncthreads();
    m = red[0];
    __syncthreads();
    float e0 = expf(v.x - m), e1 = expf(v.y - m), e2 = expf(v.z - m), e3 = expf(v.w - m);
    float s = e0 + e1 + e2 + e3;
    #pragma unroll
    for (int o = 16; o > 0; o >>= 1) s += __shfl_xor_sync(0xffffffffu, s, o);
    if ((tid & 31) == 0) red[tid >> 5] = s;
    __syncthreads();
    if (tid == 0) {
        float ss = 0.f;
        #pragma unroll
        for (int i = 0; i < 8; i++) ss += red[i];
        red[0] = ss;
    }
    __syncthreads();
    const float inv = 1.0f / red[0];
    unsigned char* ah = g_ath + (size_t)b * AB;
    st_one(ah, 1024, u0 >> 6, t, u0 & 63, e0 * inv, e1 * inv);
    st_one(ah, 1024, u0 >> 6, t, (u0 & 63) + 2, e2 * inv, e3 * inv);
}

// ---------------------------------------------------------------------------
// gemm_av: 1-term (attn single fp16). O[t,c] = attn·Vᵀ, K causal.
// CTA 128(t) x 64(c), warps 4m x 2n (warp 32x32). grid (8, 8, Bb). smem 2x32KB.
// ---------------------------------------------------------------------------
__global__ __launch_bounds__(256) void gemm_av()
{
    extern __shared__ char sm[];
    const uint32_t smb = s2u(sm);
    const int tid = threadIdx.x, wid = tid >> 5, lane = tid & 31;
    const int wm = wid & 3, wn = wid >> 2;
    const int b = blockIdx.z, m0 = blockIdx.y * 128, n0 = blockIdx.x * 64;

    const unsigned char* ah = g_ath + (size_t)b * AB;
    const unsigned char* vrh = g_vreh + (size_t)b * VB;
    const unsigned char* vih = g_vimh + (size_t)b * VB;

    auto issue = [&](int ch, uint32_t bs) {
        size_t ao = ((size_t)(ch * 1024 + m0)) << 7;
        size_t bo = ((size_t)(ch * 512 + n0)) << 7;
        cpreg(bs + 0,     ah + ao, 16384, tid);
        cpreg(bs + 16384, vrh + bo, 8192, tid);
        cpreg(bs + 24576, vih + bo, 8192, tid);
    };

    float mR[2][4][4] = {}, mI[2][4][4] = {};
    const int nch = m0 / 64 + 2;
    issue(0, smb); cpa_commit();
    for (int ch = 0; ch < nch; ch++) {
        uint32_t base = smb + (ch & 1) * WB_STRIDE;
        if (ch + 1 < nch) { issue(ch + 1, smb + ((ch + 1) & 1) * WB_STRIDE); cpa_commit(); cpa_wait1(); }
        else cpa_wait0();
        __syncthreads();
        #pragma unroll
        for (int ks = 0; ks < 4; ks++) {
            uint32_t rH[8], iH[8];
            ldsm4(rH + 0, b_addr(base + 16384, wn * 32,      ks, lane));
            ldsm4(rH + 4, b_addr(base + 16384, wn * 32 + 16, ks, lane));
            ldsm4(iH + 0, b_addr(base + 24576, wn * 32,      ks, lane));
            ldsm4(iH + 4, b_addr(base + 24576, wn * 32 + 16, ks, lane));
            #pragma unroll
            for (int mi = 0; mi < 2; mi++) {
                uint32_t aH[4];
                ldsm4(aH, a_addr(base + 0, wm * 32 + mi * 16, ks, lane));
                #pragma unroll
                for (int nf = 0; nf < 4; nf++) {
                    mma16816(mR[mi][nf], aH, rH + nf * 2);
                    mma16816(mI[mi][nf], aH, iH + nf * 2);
                }
            }
        }
        __syncthreads();
    }

    unsigned char* orh = g_oreh + (size_t)b * OB;
    unsigned char* oih = g_oimh + (size_t)b * OB;
    const int g = lane >> 2, cp = (lane & 3) * 2;
    #pragma unroll
    for (int mi = 0; mi < 2; mi++) {
        const int r0 = m0 + wm * 32 + mi * 16 + g;
        #pragma unroll
        for (int nf = 0; nf < 4; nf++) {
            const int c = wn * 32 + nf * 8 + cp;
            const int och = (n0 + c) >> 6, oc = (n0 + c) & 63;
            float* aR = mR[mi][nf];
            float* aI = mI[mi][nf];
            st_one(orh, 1024, och, r0, oc, aR[0], aR[1]);
            st_one(oih, 1024, och, r0, oc, aI[0], aI[1]);
            st_one(orh, 1024, och, r0 + 8, oc, aR[2], aR[3]);
            st_one(oih, 1024, och, r0 + 8, oc, aI[2], aI[3]);
        }
    }
}

// ---------------------------------------------------------------------------
extern "C" void kernel_launch(void* const* d_in, const int* in_sizes, int n_in,
                              void* d_out, int out_size)
{
    const float* z_re  = (const float*)d_in[0];
    const float* z_im  = (const float*)d_in[1];
    const float* Wq    = (const float*)d_in[2];
    const float* phi_q = (const float*)d_in[3];
    const float* Wk    = (const float*)d_in[4];
    const float* phi_k = (const float*)d_in[5];
    const float* Wv    = (const float*)d_in[6];
    const float* phi_v = (const float*)d_in[7];
    const float* Wo    = (const float*)d_in[8];
    const float* phi_o = (const float*)d_in[9];

    unsigned char *wh, *zh;
    unsigned char *oreh, *oimh;
    cudaGetSymbolAddress((void**)&wh, g_wh);
    cudaGetSymbolAddress((void**)&zh, g_zh);
    cudaGetSymbolAddress((void**)&oreh, g_oreh);
    cudaGetSymbolAddress((void**)&oimh, g_oimh);

    cudaFuncSetAttribute(gemm_qk2,      cudaFuncAttributeMaxDynamicSharedMemorySize, QK2_SM);
    cudaFuncSetAttribute(gemm_wB<true>, cudaFuncAttributeMaxDynamicSharedMemorySize, WB_SM);
    cudaFuncSetAttribute(gemm_wB<false>,cudaFuncAttributeMaxDynamicSharedMemorySize, WB_SM);
    cudaFuncSetAttribute(gemm_scores,   cudaFuncAttributeMaxDynamicSharedMemorySize, SC_SM);
    cudaFuncSetAttribute(gemm_av,       cudaFuncAttributeMaxDynamicSharedMemorySize, WB_SM);

    float* out_re = (float*)d_out;
    float* out_im = out_re + (size_t)BCT;

    prep_z<<<dim3(32, 8, Bb), 256>>>(z_re, z_im);
    prep_w<<<dim3(8, 4), 256>>>(Wq, Wk, Wv, Wo);
    gemm_qk2<<<dim3(8, 8, Bb), 256, QK2_SM>>>(phi_q, phi_k);
    gemm_wB<true><<<dim3(16, 4, Bb), 256, WB_SM>>>(wh + 2*WBY, phi_v,
        zh, zh + (size_t)8*1024*128, ZB16, nullptr, nullptr);
    gemm_scores<<<dim3(16, 8, Bb), 256, SC_SM>>>();
    softmax_kernel<<<dim3(Tt, Bb), 256>>>();
    gemm_av<<<dim3(8, 8, Bb), 256, WB_SM>>>();
    gemm_wB<false><<<dim3(16, 4, Bb), 256, WB_SM>>>(wh + 3*WBY, phi_o,
        oreh, oimh, OB, out_re, out_im);
}

// round 14
// speedup vs baseline: 1.5009x; 1.5009x over previous
#include <cuda_runtime.h>
#include <cuda_fp16.h>
#include <cstdint>
#include <math.h>

#define Bb 8
#define Cc 512
#define Tt 1024
#define BCT (Bb*Cc*Tt)
#define BTT (Bb*Tt*Tt)

// chunked fp16 layout: [ch][R rows][128B], per-row swizzle:
// byte(col,row) = (col*2) ^ ((row&7)<<4)
#define ZB16 ((size_t)16*1024*128)
#define VB   ((size_t)16*512*128)
#define AB   ((size_t)16*1024*128)
#define OB   ((size_t)8*1024*128)
#define WBY  ((size_t)8*512*128)

__device__ __align__(16) unsigned char g_zh[Bb*ZB16], g_zl[Bb*ZB16];
__device__ __align__(16) unsigned char g_qh[Bb*ZB16], g_ql[Bb*ZB16];
__device__ __align__(16) unsigned char g_kh[Bb*ZB16], g_kl[Bb*ZB16];
__device__ __align__(16) unsigned char g_vreh[Bb*VB], g_vimh[Bb*VB];
__device__ __align__(16) unsigned char g_ath[Bb*AB];
__device__ __align__(16) unsigned char g_oreh[Bb*OB], g_oimh[Bb*OB];
__device__ __align__(16) unsigned char g_wh[4*WBY],   g_wl[4*WBY];
__device__ float g_attn[BTT];

#define SW128(o) ((o) ^ (((o) >> 3) & 0x70))
#define CPT 256

__device__ __forceinline__ uint32_t s2u(const void* p) {
    uint32_t a;
    asm("{ .reg .u64 t; cvta.to.shared.u64 t, %1; cvt.u32.u64 %0, t; }" : "=r"(a) : "l"(p));
    return a;
}
__device__ __forceinline__ uint32_t pk2(__half a, __half b) {
    return ((uint32_t)__half_as_ushort(b) << 16) | (uint32_t)__half_as_ushort(a);
}
__device__ __forceinline__ void st_pair(unsigned char* bh, unsigned char* bl,
                                        int R, int ch, int row, int col, float v0, float v1) {
    size_t off = (((size_t)ch * R + row) << 7) + (uint32_t)((col * 2) ^ ((row & 7) << 4));
    __half h0 = __float2half_rn(v0), h1 = __float2half_rn(v1);
    *(uint32_t*)(bh + off) = pk2(h0, h1);
    __half l0 = __float2half_rn(v0 - __half2float(h0));
    __half l1 = __float2half_rn(v1 - __half2float(h1));
    *(uint32_t*)(bl + off) = pk2(l0, l1);
}
__device__ __forceinline__ void st_one(unsigned char* bh,
                                       int R, int ch, int row, int col, float v0, float v1) {
    size_t off = (((size_t)ch * R + row) << 7) + (uint32_t)((col * 2) ^ ((row & 7) << 4));
    *(uint32_t*)(bh + off) = pk2(__float2half_rn(v0), __float2half_rn(v1));
}
__device__ __forceinline__ void cpa16(uint32_t s, const void* g) {
    asm volatile("cp.async.cg.shared.global [%0], [%1], 16;" :: "r"(s), "l"(g) : "memory");
}
__device__ __forceinline__ void cpa_commit() { asm volatile("cp.async.commit_group;" ::: "memory"); }
__device__ __forceinline__ void cpa_wait1()  { asm volatile("cp.async.wait_group 1;" ::: "memory"); }
__device__ __forceinline__ void cpa_wait0()  { asm volatile("cp.async.wait_group 0;" ::: "memory"); }
__device__ __forceinline__ void cpreg(uint32_t s, const void* g, int nbytes, int tid) {
    for (int o = tid * 16; o < nbytes; o += CPT * 16) cpa16(s + o, (const unsigned char*)g + o);
}
__device__ __forceinline__ void ldsm4(uint32_t* r, uint32_t addr) {
    asm volatile("ldmatrix.sync.aligned.m8n8.x4.shared.b16 {%0,%1,%2,%3}, [%4];"
                 : "=r"(r[0]), "=r"(r[1]), "=r"(r[2]), "=r"(r[3]) : "r"(addr));
}
__device__ __forceinline__ void mma16816(float* d, const uint32_t* a, const uint32_t* b) {
    asm volatile(
        "mma.sync.aligned.m16n8k16.row.col.f32.f16.f16.f32 "
        "{%0,%1,%2,%3}, {%4,%5,%6,%7}, {%8,%9}, {%0,%1,%2,%3};"
        : "+f"(d[0]), "+f"(d[1]), "+f"(d[2]), "+f"(d[3])
        : "r"(a[0]), "r"(a[1]), "r"(a[2]), "r"(a[3]), "r"(b[0]), "r"(b[1]));
}
__device__ __forceinline__ void mma16816h(uint32_t* d, const uint32_t* a, const uint32_t* b) {
    asm volatile(
        "mma.sync.aligned.m16n8k16.row.col.f16.f16.f16.f16 "
        "{%0,%1}, {%2,%3,%4,%5}, {%6,%7}, {%0,%1};"
        : "+r"(d[0]), "+r"(d[1])
        : "r"(a[0]), "r"(a[1]), "r"(a[2]), "r"(a[3]), "r"(b[0]), "r"(b[1]));
}
__device__ __forceinline__ void addcorr(float* d, const uint32_t* c) {
    __half2 h0 = *(const __half2*)&c[0];
    __half2 h1 = *(const __half2*)&c[1];
    d[0] += __half2float(h0.x); d[1] += __half2float(h0.y);
    d[2] += __half2float(h1.x); d[3] += __half2float(h1.y);
}
__device__ __forceinline__ void mma_split(float* d, const uint32_t* aH, const uint32_t* aL,
                                          const uint32_t* bH, const uint32_t* bL) {
    mma16816(d, aH, bH);
    mma16816(d, aH, bL);
    mma16816(d, aL, bH);
}
__device__ __forceinline__ uint32_t a_addr(uint32_t base, int mbase, int ks, int lane) {
    int row = mbase + (lane & 15);
    int byt = ks * 32 + ((lane >> 4) << 4);
    return base + SW128((uint32_t)(row * 128 + byt));
}
__device__ __forceinline__ uint32_t b_addr(uint32_t base, int nbase, int ks, int lane) {
    int row = nbase + ((lane >> 4) << 3) + (lane & 7);
    int byt = ks * 32 + (((lane >> 3) & 1) << 4);
    return base + SW128((uint32_t)(row * 128 + byt));
}

// ---------------------------------------------------------------------------
__global__ __launch_bounds__(256) void prep_z(
    const float* __restrict__ zre, const float* __restrict__ zim)
{
    __shared__ float sre[64][33], sim[64][33];
    const int b = blockIdx.z, t0 = blockIdx.x * 32, c0 = blockIdx.y * 64;
    const int tid = threadIdx.x;
    const float* pre = zre + (size_t)b * Cc * Tt;
    const float* pim = zim + (size_t)b * Cc * Tt;
    for (int i = tid; i < 2048; i += 256) {
        int cl = i >> 5, tl = i & 31;
        sre[cl][tl] = pre[(size_t)(c0 + cl) * Tt + t0 + tl];
        sim[cl][tl] = pim[(size_t)(c0 + cl) * Tt + t0 + tl];
    }
    __syncthreads();
    unsigned char* zh = g_zh + (size_t)b * ZB16;
    unsigned char* zl = g_zl + (size_t)b * ZB16;
    const int ch = c0 >> 6;
    for (int i = tid; i < 1024; i += 256) {
        int tl = i >> 5, p = i & 31;
        int t = t0 + tl, col = p * 2;
        st_pair(zh, zl, 1024, ch,     t, col, sre[col][tl], sre[col + 1][tl]);
        st_pair(zh, zl, 1024, ch + 8, t, col, sim[col][tl], sim[col + 1][tl]);
    }
}

// ---------------------------------------------------------------------------
__global__ __launch_bounds__(256) void prep_w(
    const float* __restrict__ W0, const float* __restrict__ W1,
    const float* __restrict__ W2, const float* __restrict__ W3)
{
    const int d0 = blockIdx.x * 64, wi = blockIdx.y, tid = threadIdx.x;
    const float* W = (wi == 0) ? W0 : (wi == 1) ? W1 : (wi == 2) ? W2 : W3;
    unsigned char* oh = g_wh + (size_t)wi * WBY;
    unsigned char* ol = g_wl + (size_t)wi * WBY;
    for (int i = tid; i < 8192; i += 256) {
        int dl = i >> 7, q = i & 127;
        int c = q * 4, d = d0 + dl;
        float4 v = *(const float4*)&W[(size_t)d * Cc + c];
        st_pair(oh, ol, 512, c >> 6, d, c & 63, v.x, v.y);
        st_pair(oh, ol, 512, c >> 6, d, (c & 63) + 2, v.z, v.w);
    }
}

// ---------------------------------------------------------------------------
// gemm_qk2: fused Q+K projection, 3-term f32 acc.
// CTA 128(t)x64(d), 8 warps = 4m x 2n, warp 32x32 for BOTH Q and K.
// grid (8, 8, Bb). smem 2 x 96KB.
// ---------------------------------------------------------------------------
#define QK2_STRIDE 98304
#define QK2_SM (2*QK2_STRIDE)
__global__ __launch_bounds__(256) void gemm_qk2(
    const float* __restrict__ phi_q, const float* __restrict__ phi_k)
{
    extern __shared__ char sm[];
    __shared__ float csq[64], snq[64], csk[64], snk[64];
    const uint32_t smb = s2u(sm);
    const int tid = threadIdx.x, wid = tid >> 5, lane = tid & 31;
    const int wm = wid & 3, wn = wid >> 2;
    const int b = blockIdx.z, m0 = blockIdx.y * 128, n0 = blockIdx.x * 64;

    if (tid < 64) {
        float s, c;
        sincosf(phi_q[n0 + tid], &s, &c); csq[tid] = c; snq[tid] = s;
        sincosf(phi_k[n0 + tid], &s, &c); csk[tid] = c; snk[tid] = s;
    }

    const unsigned char* zh = g_zh + (size_t)b * ZB16;
    const unsigned char* zl = g_zl + (size_t)b * ZB16;
    const unsigned char* wqh = g_wh;
    const unsigned char* wql = g_wl;
    const unsigned char* wkh = g_wh + WBY;
    const unsigned char* wkl = g_wl + WBY;

    auto issue = [&](int ch, uint32_t bs) {
        size_t aoR = ((size_t)(ch * 1024 + m0)) << 7;
        size_t aoI = ((size_t)((ch + 8) * 1024 + m0)) << 7;
        size_t bo  = ((size_t)(ch * 512 + n0)) << 7;
        cpreg(bs + 0,     zh + aoR, 16384, tid);
        cpreg(bs + 16384, zl + aoR, 16384, tid);
        cpreg(bs + 32768, zh + aoI, 16384, tid);
        cpreg(bs + 49152, zl + aoI, 16384, tid);
        cpreg(bs + 65536, wqh + bo, 8192, tid);
        cpreg(bs + 73728, wql + bo, 8192, tid);
        cpreg(bs + 81920, wkh + bo, 8192, tid);
        cpreg(bs + 90112, wkl + bo, 8192, tid);
    };

    float accQR[2][4][4] = {}, accQI[2][4][4] = {};
    float accKR[2][4][4] = {}, accKI[2][4][4] = {};
    issue(0, smb); cpa_commit();
    for (int ch = 0; ch < 8; ch++) {
        uint32_t base = smb + (ch & 1) * QK2_STRIDE;
        if (ch + 1 < 8) { issue(ch + 1, smb + ((ch + 1) & 1) * QK2_STRIDE); cpa_commit(); cpa_wait1(); }
        else cpa_wait0();
        __syncthreads();
        #pragma unroll
        for (int ks = 0; ks < 4; ks++) {
            uint32_t arH[8], arL[8], aiH[8], aiL[8];
            ldsm4(arH + 0, a_addr(base + 0,     wm * 32,      ks, lane));
            ldsm4(arH + 4, a_addr(base + 0,     wm * 32 + 16, ks, lane));
            ldsm4(arL + 0, a_addr(base + 16384, wm * 32,      ks, lane));
            ldsm4(arL + 4, a_addr(base + 16384, wm * 32 + 16, ks, lane));
            ldsm4(aiH + 0, a_addr(base + 32768, wm * 32,      ks, lane));
            ldsm4(aiH + 4, a_addr(base + 32768, wm * 32 + 16, ks, lane));
            ldsm4(aiL + 0, a_addr(base + 49152, wm * 32,      ks, lane));
            ldsm4(aiL + 4, a_addr(base + 49152, wm * 32 + 16, ks, lane));
            uint32_t bH[8], bL[8];
            ldsm4(bH + 0, b_addr(base + 65536, wn * 32,      ks, lane));
            ldsm4(bH + 4, b_addr(base + 65536, wn * 32 + 16, ks, lane));
            ldsm4(bL + 0, b_addr(base + 73728, wn * 32,      ks, lane));
            ldsm4(bL + 4, b_addr(base + 73728, wn * 32 + 16, ks, lane));
            #pragma unroll
            for (int mi = 0; mi < 2; mi++)
                #pragma unroll
                for (int nf = 0; nf < 4; nf++) {
                    mma_split(accQR[mi][nf], arH + mi * 4, arL + mi * 4, bH + nf * 2, bL + nf * 2);
                    mma_split(accQI[mi][nf], aiH + mi * 4, aiL + mi * 4, bH + nf * 2, bL + nf * 2);
                }
            ldsm4(bH + 0, b_addr(base + 81920, wn * 32,      ks, lane));
            ldsm4(bH + 4, b_addr(base + 81920, wn * 32 + 16, ks, lane));
            ldsm4(bL + 0, b_addr(base + 90112, wn * 32,      ks, lane));
            ldsm4(bL + 4, b_addr(base + 90112, wn * 32 + 16, ks, lane));
            #pragma unroll
            for (int mi = 0; mi < 2; mi++)
                #pragma unroll
                for (int nf = 0; nf < 4; nf++) {
                    mma_split(accKR[mi][nf], arH + mi * 4, arL + mi * 4, bH + nf * 2, bL + nf * 2);
                    mma_split(accKI[mi][nf], aiH + mi * 4, aiL + mi * 4, bH + nf * 2, bL + nf * 2);
                }
        }
        __syncthreads();
    }

    unsigned char* qh = g_qh + (size_t)b * ZB16;
    unsigned char* ql = g_ql + (size_t)b * ZB16;
    unsigned char* kh = g_kh + (size_t)b * ZB16;
    unsigned char* kl = g_kl + (size_t)b * ZB16;
    const int g = lane >> 2, cp = (lane & 3) * 2, och = n0 >> 6;
    #pragma unroll
    for (int mi = 0; mi < 2; mi++) {
        const int r0 = m0 + wm * 32 + mi * 16 + g;
        #pragma unroll
        for (int nf = 0; nf < 4; nf++) {
            const int c = wn * 32 + nf * 8 + cp;
            float cq0 = csq[c], sq0 = snq[c], cq1 = csq[c + 1], sq1 = snq[c + 1];
            float ck0 = csk[c], sk0 = snk[c], ck1 = csk[c + 1], sk1 = snk[c + 1];
            float* qR = accQR[mi][nf]; float* qI = accQI[mi][nf];
            float* kR = accKR[mi][nf]; float* kI = accKI[mi][nf];
            st_pair(qh, ql, 1024, och,     r0, c, qR[0]*cq0 - qI[0]*sq0, qR[1]*cq1 - qI[1]*sq1);
            st_pair(qh, ql, 1024, och + 8, r0, c, qR[0]*sq0 + qI[0]*cq0, qR[1]*sq1 + qI[1]*cq1);
            st_pair(qh, ql, 1024, och,     r0 + 8, c, qR[2]*cq0 - qI[2]*sq0, qR[3]*cq1 - qI[3]*sq1);
            st_pair(qh, ql, 1024, och + 8, r0 + 8, c, qR[2]*sq0 + qI[2]*cq0, qR[3]*sq1 + qI[3]*cq1);
            st_pair(kh, kl, 1024, och,     r0, c, kR[0]*ck0 - kI[0]*sk0, kR[1]*ck1 - kI[1]*sk1);
            st_pair(kh, kl, 1024, och + 8, r0, c, kR[0]*sk0 + kI[0]*ck0, kR[1]*sk1 + kI[1]*ck1);
            st_pair(kh, kl, 1024, och,     r0 + 8, c, kR[2]*ck0 - kI[2]*sk0, kR[3]*ck1 - kI[3]*sk1);
            st_pair(kh, kl, 1024, och + 8, r0 + 8, c, kR[2]*sk0 + kI[2]*ck0, kR[3]*sk1 + kI[3]*ck1);
        }
    }
}

// ---------------------------------------------------------------------------
// gemm_scores: 3-term (main f32 + 2 corr f16), concatenated K=1024.
// CTA 128x128, warps 2m x 4n (warp 64x32). grid (8, 8, Bb). smem 2x64KB.
// ---------------------------------------------------------------------------
#define SC_STRIDE 65536
#define SC_SM (2*SC_STRIDE)
__global__ __launch_bounds__(256) void gemm_scores()
{
    extern __shared__ char sm[];
    const uint32_t smb = s2u(sm);
    const int tid = threadIdx.x, wid = tid >> 5, lane = tid & 31;
    const int wm = wid & 1, wn = wid >> 1;
    const int b = blockIdx.z, m0 = blockIdx.y * 128, n0 = blockIdx.x * 128;
    if (n0 >= m0 + 128) return;
    float* arow = g_attn + (size_t)b * Tt * Tt;

    const unsigned char* qh = g_qh + (size_t)b * ZB16;
    const unsigned char* ql = g_ql + (size_t)b * ZB16;
    const unsigned char* kh = g_kh + (size_t)b * ZB16;
    const unsigned char* kl = g_kl + (size_t)b * ZB16;

    auto issue = [&](int ch, uint32_t bs) {
        size_t ao = ((size_t)(ch * 1024 + m0)) << 7;
        size_t bo = ((size_t)(ch * 1024 + n0)) << 7;
        cpreg(bs + 0,     qh + ao, 16384, tid);
        cpreg(bs + 16384, ql + ao, 16384, tid);
        cpreg(bs + 32768, kh + bo, 16384, tid);
        cpreg(bs + 49152, kl + bo, 16384, tid);
    };

    float acc[4][4][4] = {};
    uint32_t accC[4][4][2] = {};
    issue(0, smb); cpa_commit();
    for (int ch = 0; ch < 16; ch++) {
        uint32_t base = smb + (ch & 1) * SC_STRIDE;
        if (ch + 1 < 16) { issue(ch + 1, smb + ((ch + 1) & 1) * SC_STRIDE); cpa_commit(); cpa_wait1(); }
        else cpa_wait0();
        __syncthreads();
        #pragma unroll
        for (int ks = 0; ks < 4; ks++) {
            uint32_t bH[8], bL[8];
            ldsm4(bH + 0, b_addr(base + 32768, wn * 32,      ks, lane));
            ldsm4(bH + 4, b_addr(base + 32768, wn * 32 + 16, ks, lane));
            ldsm4(bL + 0, b_addr(base + 49152, wn * 32,      ks, lane));
            ldsm4(bL + 4, b_addr(base + 49152, wn * 32 + 16, ks, lane));
            #pragma unroll
            for (int mi = 0; mi < 4; mi++) {
                uint32_t aH[4], aL[4];
                ldsm4(aH, a_addr(base + 0,     wm * 64 + mi * 16, ks, lane));
                ldsm4(aL, a_addr(base + 16384, wm * 64 + mi * 16, ks, lane));
                #pragma unroll
                for (int nf = 0; nf < 4; nf++) {
                    mma16816(acc[mi][nf], aH, bH + nf * 2);
                    mma16816h(accC[mi][nf], aH, bL + nf * 2);
                    mma16816h(accC[mi][nf], aL, bH + nf * 2);
                }
            }
        }
        __syncthreads();
    }

    const int g = lane >> 2, cp = (lane & 3) * 2;
    #pragma unroll
    for (int mi = 0; mi < 4; mi++) {
        const int r0 = m0 + wm * 64 + mi * 16 + g;
        #pragma unroll
        for (int nf = 0; nf < 4; nf++) {
            const int u = n0 + wn * 32 + nf * 8 + cp;
            float* a = acc[mi][nf];
            addcorr(a, accC[mi][nf]);
            *(float2*)&arow[(size_t)r0 * Tt + u]       = make_float2(a[0] * 0.125f, a[1] * 0.125f);
            *(float2*)&arow[(size_t)(r0 + 8) * Tt + u] = make_float2(a[2] * 0.125f, a[3] * 0.125f);
        }
    }
}

// ---------------------------------------------------------------------------
// gemm_wB: 1-term (W single fp16). D[d,n]=rot_row(W·Bᵀ).
// CTA 128(d) x 64(n), warps 4m x 2n (warp 32x32). grid (16, 4, Bb). smem 2x32KB.
// ---------------------------------------------------------------------------
#define WB_STRIDE 32768
#define WB_SM (2*WB_STRIDE)
template<bool F16OUT>
__global__ __launch_bounds__(256) void gemm_wB(
    const unsigned char* __restrict__ wh,
    const float* __restrict__ phi,
    const unsigned char* __restrict__ breh, const unsigned char* __restrict__ bimh,
    size_t bstride,
    float* __restrict__ fre, float* __restrict__ fim)
{
    extern __shared__ char sm[];
    __shared__ float s_cs[128], s_sn[128];
    const uint32_t smb = s2u(sm);
    const int tid = threadIdx.x, wid = tid >> 5, lane = tid & 31;
    const int wm = wid & 3, wn = wid >> 2;
    const int b = blockIdx.z, m0 = blockIdx.y * 128, n0 = blockIdx.x * 64;

    if (tid < 128) {
        float s, c; sincosf(phi[m0 + tid], &s, &c);
        s_cs[tid] = c; s_sn[tid] = s;
    }

    const unsigned char* brh = breh + (size_t)b * bstride;
    const unsigned char* bih = bimh + (size_t)b * bstride;

    auto issue = [&](int ch, uint32_t bs) {
        size_t ao = ((size_t)(ch * 512 + m0)) << 7;
        size_t bo = ((size_t)(ch * 1024 + n0)) << 7;
        cpreg(bs + 0,     wh + ao, 16384, tid);
        cpreg(bs + 16384, brh + bo, 8192, tid);
        cpreg(bs + 24576, bih + bo, 8192, tid);
    };

    float mR[2][4][4] = {}, mI[2][4][4] = {};
    issue(0, smb); cpa_commit();
    for (int ch = 0; ch < 8; ch++) {
        uint32_t base = smb + (ch & 1) * WB_STRIDE;
        if (ch + 1 < 8) { issue(ch + 1, smb + ((ch + 1) & 1) * WB_STRIDE); cpa_commit(); cpa_wait1(); }
        else cpa_wait0();
        __syncthreads();
        #pragma unroll
        for (int ks = 0; ks < 4; ks++) {
            uint32_t rH[8], iH[8];
            ldsm4(rH + 0, b_addr(base + 16384, wn * 32,      ks, lane));
            ldsm4(rH + 4, b_addr(base + 16384, wn * 32 + 16, ks, lane));
            ldsm4(iH + 0, b_addr(base + 24576, wn * 32,      ks, lane));
            ldsm4(iH + 4, b_addr(base + 24576, wn * 32 + 16, ks, lane));
            #pragma unroll
            for (int mi = 0; mi < 2; mi++) {
                uint32_t aH[4];
                ldsm4(aH, a_addr(base + 0, wm * 32 + mi * 16, ks, lane));
                #pragma unroll
                for (int nf = 0; nf < 4; nf++) {
                    mma16816(mR[mi][nf], aH, rH + nf * 2);
                    mma16816(mI[mi][nf], aH, iH + nf * 2);
                }
            }
        }
        __syncthreads();
    }

    const int g = lane >> 2, cp = (lane & 3) * 2;
    #pragma unroll
    for (int mi = 0; mi < 2; mi++) {
        const int lr = wm * 32 + mi * 16 + g;
        const float c0 = s_cs[lr], s0 = s_sn[lr], c8 = s_cs[lr + 8], s8 = s_sn[lr + 8];
        const int r0 = m0 + lr;
        #pragma unroll
        for (int nf = 0; nf < 4; nf++) {
            const int c = wn * 32 + nf * 8 + cp;
            float* aR = mR[mi][nf];
            float* aI = mI[mi][nf];
            float xr0 = aR[0]*c0 - aI[0]*s0, xr1 = aR[1]*c0 - aI[1]*s0;
            float xi0 = aR[0]*s0 + aI[0]*c0, xi1 = aR[1]*s0 + aI[1]*c0;
            float yr0 = aR[2]*c8 - aI[2]*s8, yr1 = aR[3]*c8 - aI[3]*s8;
            float yi0 = aR[2]*s8 + aI[2]*c8, yi1 = aR[3]*s8 + aI[3]*c8;
            if (F16OUT) {
                unsigned char* vrh = g_vreh + (size_t)b * VB;
                unsigned char* vih = g_vimh + (size_t)b * VB;
                const int och = (n0 + c) >> 6, oc = (n0 + c) & 63;
                st_one(vrh, 512, och, r0, oc, xr0, xr1);
                st_one(vih, 512, och, r0, oc, xi0, xi1);
                st_one(vrh, 512, och, r0 + 8, oc, yr0, yr1);
                st_one(vih, 512, och, r0 + 8, oc, yi0, yi1);
            } else {
                float* dre = fre + (size_t)b * Cc * Tt;
                float* dim = fim + (size_t)b * Cc * Tt;
                *(float2*)&dre[(size_t)r0 * Tt + n0 + c]       = make_float2(xr0, xr1);
                *(float2*)&dim[(size_t)r0 * Tt + n0 + c]       = make_float2(xi0, xi1);
                *(float2*)&dre[(size_t)(r0 + 8) * Tt + n0 + c] = make_float2(yr0, yr1);
                *(float2*)&dim[(size_t)(r0 + 8) * Tt + n0 + c] = make_float2(yi0, yi1);
            }
        }
    }
}

// ---------------------------------------------------------------------------
__global__ __launch_bounds__(256) void softmax_kernel()
{
    const int t = blockIdx.x, b = blockIdx.y;
    const float* row = g_attn + ((size_t)b * Tt + t) * Tt;
    const int tid = threadIdx.x;
    const float ni = __int_as_float(0xff800000);
    const int u0 = tid * 4;
    float4 v = ((const float4*)row)[tid];
    if (u0     > t) v.x = ni;
    if (u0 + 1 > t) v.y = ni;
    if (u0 + 2 > t) v.z = ni;
    if (u0 + 3 > t) v.w = ni;
    float m = fmaxf(fmaxf(v.x, v.y), fmaxf(v.z, v.w));
    __shared__ float red[8];
    #pragma unroll
    for (int o = 16; o > 0; o >>= 1) m = fmaxf(m, __shfl_xor_sync(0xffffffffu, m, o));
    if ((tid & 31) == 0) red[tid >> 5] = m;
    __syncthreads();
    if (tid == 0) {
        float mm = red[0];
        #pragma unroll
        for (int i = 1; i < 8; i++) mm = fmaxf(mm, red[i]);
        red[0] = mm;
    }
    __syncthreads();
    m = red[0];
    __syncthreads();
    float e0 = expf(v.x - m), e1 = expf(v.y - m), e2 = expf(v.z - m), e3 = expf(v.w - m);
    float s = e0 + e1 + e2 + e3;
    #pragma unroll
    for (int o = 16; o > 0; o >>= 1) s += __shfl_xor_sync(0xffffffffu, s, o);
    if ((tid & 31) == 0) red[tid >> 5] = s;
    __syncthreads();
    if (tid == 0) {
        float ss = 0.f;
        #pragma unroll
        for (int i = 0; i < 8; i++) ss += red[i];
        red[0] = ss;
    }
    __syncthreads();
    const float inv = 1.0f / red[0];
    unsigned char* ah = g_ath + (size_t)b * AB;
    st_one(ah, 1024, u0 >> 6, t, u0 & 63, e0 * inv, e1 * inv);
    st_one(ah, 1024, u0 >> 6, t, (u0 & 63) + 2, e2 * inv, e3 * inv);
}

// ---------------------------------------------------------------------------
// gemm_av: 1-term (attn single fp16). O[t,c] = attn·Vᵀ, K causal.
// CTA 128(t) x 64(c), warps 4m x 2n (warp 32x32). grid (8, 8, Bb). smem 2x32KB.
// ---------------------------------------------------------------------------
__global__ __launch_bounds__(256) void gemm_av()
{
    extern __shared__ char sm[];
    const uint32_t smb = s2u(sm);
    const int tid = threadIdx.x, wid = tid >> 5, lane = tid & 31;
    const int wm = wid & 3, wn = wid >> 2;
    const int b = blockIdx.z, m0 = blockIdx.y * 128, n0 = blockIdx.x * 64;

    const unsigned char* ah = g_ath + (size_t)b * AB;
    const unsigned char* vrh = g_vreh + (size_t)b * VB;
    const unsigned char* vih = g_vimh + (size_t)b * VB;

    auto issue = [&](int ch, uint32_t bs) {
        size_t ao = ((size_t)(ch * 1024 + m0)) << 7;
        size_t bo = ((size_t)(ch * 512 + n0)) << 7;
        cpreg(bs + 0,     ah + ao, 16384, tid);
        cpreg(bs + 16384, vrh + bo, 8192, tid);
        cpreg(bs + 24576, vih + bo, 8192, tid);
    };

    float mR[2][4][4] = {}, mI[2][4][4] = {};
    const int nch = m0 / 64 + 2;
    issue(0, smb); cpa_commit();
    for (int ch = 0; ch < nch; ch++) {
        uint32_t base = smb + (ch & 1) * WB_STRIDE;
        if (ch + 1 < nch) { issue(ch + 1, smb + ((ch + 1) & 1) * WB_STRIDE); cpa_commit(); cpa_wait1(); }
        else cpa_wait0();
        __syncthreads();
        #pragma unroll
        for (int ks = 0; ks < 4; ks++) {
            uint32_t rH[8], iH[8];
            ldsm4(rH + 0, b_addr(base + 16384, wn * 32,      ks, lane));
            ldsm4(rH + 4, b_addr(base + 16384, wn * 32 + 16, ks, lane));
            ldsm4(iH + 0, b_addr(base + 24576, wn * 32,      ks, lane));
            ldsm4(iH + 4, b_addr(base + 24576, wn * 32 + 16, ks, lane));
            #pragma unroll
            for (int mi = 0; mi < 2; mi++) {
                uint32_t aH[4];
                ldsm4(aH, a_addr(base + 0, wm * 32 + mi * 16, ks, lane));
                #pragma unroll
                for (int nf = 0; nf < 4; nf++) {
                    mma16816(mR[mi][nf], aH, rH + nf * 2);
                    mma16816(mI[mi][nf], aH, iH + nf * 2);
                }
            }
        }
        __syncthreads();
    }

    unsigned char* orh = g_oreh + (size_t)b * OB;
    unsigned char* oih = g_oimh + (size_t)b * OB;
    const int g = lane >> 2, cp = (lane & 3) * 2;
    #pragma unroll
    for (int mi = 0; mi < 2; mi++) {
        const int r0 = m0 + wm * 32 + mi * 16 + g;
        #pragma unroll
        for (int nf = 0; nf < 4; nf++) {
            const int c = wn * 32 + nf * 8 + cp;
            const int och = (n0 + c) >> 6, oc = (n0 + c) & 63;
            float* aR = mR[mi][nf];
            float* aI = mI[mi][nf];
            st_one(orh, 1024, och, r0, oc, aR[0], aR[1]);
            st_one(oih, 1024, och, r0, oc, aI[0], aI[1]);
            st_one(orh, 1024, och, r0 + 8, oc, aR[2], aR[3]);
            st_one(oih, 1024, och, r0 + 8, oc, aI[2], aI[3]);
        }
    }
}

// ---------------------------------------------------------------------------
extern "C" void kernel_launch(void* const* d_in, const int* in_sizes, int n_in,
                              void* d_out, int out_size)
{
    const float* z_re  = (const float*)d_in[0];
    const float* z_im  = (const float*)d_in[1];
    const float* Wq    = (const float*)d_in[2];
    const float* phi_q = (const float*)d_in[3];
    const float* Wk    = (const float*)d_in[4];
    const float* phi_k = (const float*)d_in[5];
    const float* Wv    = (const float*)d_in[6];
    const float* phi_v = (const float*)d_in[7];
    const float* Wo    = (const float*)d_in[8];
    const float* phi_o = (const float*)d_in[9];

    unsigned char *wh, *zh;
    unsigned char *oreh, *oimh;
    cudaGetSymbolAddress((void**)&wh, g_wh);
    cudaGetSymbolAddress((void**)&zh, g_zh);
    cudaGetSymbolAddress((void**)&oreh, g_oreh);
    cudaGetSymbolAddress((void**)&oimh, g_oimh);

    cudaFuncSetAttribute(gemm_qk2,      cudaFuncAttributeMaxDynamicSharedMemorySize, QK2_SM);
    cudaFuncSetAttribute(gemm_wB<true>, cudaFuncAttributeMaxDynamicSharedMemorySize, WB_SM);
    cudaFuncSetAttribute(gemm_wB<false>,cudaFuncAttributeMaxDynamicSharedMemorySize, WB_SM);
    cudaFuncSetAttribute(gemm_scores,   cudaFuncAttributeMaxDynamicSharedMemorySize, SC_SM);
    cudaFuncSetAttribute(gemm_av,       cudaFuncAttributeMaxDynamicSharedMemorySize, WB_SM);

    float* out_re = (float*)d_out;
    float* out_im = out_re + (size_t)BCT;

    prep_z<<<dim3(32, 8, Bb), 256>>>(z_re, z_im);
    prep_w<<<dim3(8, 4), 256>>>(Wq, Wk, Wv, Wo);
    gemm_qk2<<<dim3(8, 8, Bb), 256, QK2_SM>>>(phi_q, phi_k);
    // V projection: B = z hi (re chunks 0-7, im chunks 8-15), stride ZB16
    gemm_wB<true><<<dim3(16, 4, Bb), 256, WB_SM>>>(wh + 2*WBY, phi_v,
        zh, zh + (size_t)8*1024*128, ZB16, nullptr, nullptr);
    gemm_scores<<<dim3(8, 8, Bb), 256, SC_SM>>>();
    softmax_kernel<<<dim3(Tt, Bb), 256>>>();
    gemm_av<<<dim3(8, 8, Bb), 256, WB_SM>>>();
    // Final projection: B = o hi (re/im 8-chunk tensors), stride OB
    gemm_wB<false><<<dim3(16, 4, Bb), 256, WB_SM>>>(wh + 3*WBY, phi_o,
        oreh, oimh, OB, out_re, out_im);
}